// round 10
// baseline (speedup 1.0000x reference)
#include <cuda_runtime.h>
#include <cuda_fp16.h>
#include <cstdint>

// Problem constants
#define B_      32
#define NTOK    3136
#define DIMC    768
#define DIM3    2304
#define HEADS   12
#define HD      64
#define NW      49
#define WS      16
#define TPW     64
#define MTOK    784
#define KDIM    768

#define NELEM_X   ((size_t)B_ * NTOK * DIMC)
#define NELEM_O   ((size_t)B_ * MTOK * DIMC)
#define WQT_ELEMS ((size_t)DIM3 * DIMC)
#define WPT_ELEMS ((size_t)DIMC * DIMC)

// Scratch (device globals: allocation-free rule)
__device__ __half g_qkv[(size_t)B_ * NTOK * DIM3];   // fp16 qkv
__device__ __half g_xh[NELEM_X];
__device__ __half g_oh[NELEM_O];
__device__ __half g_wt[WQT_ELEMS + WPT_ELEMS];       // [N][K] transposed, fp16

// ---------------------------------------------------------------------------
// PTX helpers
// ---------------------------------------------------------------------------
__device__ __forceinline__ uint32_t smem_u32(const void* p) {
    uint32_t a;
    asm("{ .reg .u64 t; cvta.to.shared.u64 t, %1; cvt.u32.u64 %0, t; }" : "=r"(a) : "l"(p));
    return a;
}
#define CP_ASYNC16(dst, src) \
    asm volatile("cp.async.cg.shared.global [%0], [%1], 16;" :: "r"(dst), "l"(src))
#define CP_COMMIT() asm volatile("cp.async.commit_group;" ::: "memory")
#define CP_WAIT1()  asm volatile("cp.async.wait_group 1;" ::: "memory")

#define LDSM4(r, addr) \
    asm volatile("ldmatrix.sync.aligned.m8n8.x4.shared.b16 {%0,%1,%2,%3}, [%4];" \
                 : "=r"((r)[0]), "=r"((r)[1]), "=r"((r)[2]), "=r"((r)[3]) : "r"(addr))
#define LDSM4T(r, addr) \
    asm volatile("ldmatrix.sync.aligned.m8n8.x4.trans.shared.b16 {%0,%1,%2,%3}, [%4];" \
                 : "=r"((r)[0]), "=r"((r)[1]), "=r"((r)[2]), "=r"((r)[3]) : "r"(addr))
#define STS32(addr, v) \
    asm volatile("st.shared.b32 [%0], %1;" :: "r"(addr), "r"(v))

#define MMA_F16(c, a, b0, b1) \
    asm volatile("mma.sync.aligned.m16n8k16.row.col.f32.f16.f16.f32 " \
                 "{%0,%1,%2,%3}, {%4,%5,%6,%7}, {%8,%9}, {%0,%1,%2,%3};" \
                 : "+f"((c)[0]), "+f"((c)[1]), "+f"((c)[2]), "+f"((c)[3]) \
                 : "r"((a)[0]), "r"((a)[1]), "r"((a)[2]), "r"((a)[3]), \
                   "r"(b0), "r"(b1))

// ---------------------------------------------------------------------------
// fp16 GEMM (unchanged from R9 — at fp32-acc HMMA hardware floor).
// Tile 256(M) x 128(N), 8 warps, warp tile 64x64, KC=64, 3-stage cp.async.
// ---------------------------------------------------------------------------
#define TILE_M    256
#define TILE_N    128
#define KC        64
#define B_OFF     32768
#define STG_BYTES 49152
#define NSTAGE    3
#define GEMM_SMEM (NSTAGE * STG_BYTES)  // 147456

__device__ __forceinline__ void load_stage(
    const __half* __restrict__ A, const __half* __restrict__ Bt,
    int m0, int n0, int kt, int K, uint32_t buf, int tid)
{
    #pragma unroll
    for (int i = 0; i < 12; ++i) {
        int idx = tid + i * 256;
        int mat = idx >> 11;
        int c   = idx & 2047;
        int r   = c >> 3;
        int g   = c & 7;
        const __half* src = (mat ? Bt : A)
                          + (size_t)((mat ? n0 : m0) + r) * K + kt + g * 8;
        uint32_t dst = buf + mat * B_OFF + r * 128 + ((g ^ (r & 7)) * 16);
        CP_ASYNC16(dst, src);
    }
    CP_COMMIT();
}

template <int OUT_HALF>
__global__ __launch_bounds__(256, 1)
void gemm_f16_kernel(const __half* __restrict__ A, const __half* __restrict__ Bt,
                     const float* __restrict__ bias, void* __restrict__ Cv,
                     int M, int N, int K)
{
    extern __shared__ char smem[];
    const uint32_t sb = smem_u32(smem);
    const int tid = threadIdx.x, wid = tid >> 5, lane = tid & 31;
    const int wm = wid & 3, wn = wid >> 2;
    const int m0 = blockIdx.y * TILE_M;
    const int n0 = blockIdx.x * TILE_N;

    float acc[4][8][4];
    #pragma unroll
    for (int mt = 0; mt < 4; ++mt)
        #pragma unroll
        for (int nt = 0; nt < 8; ++nt)
            #pragma unroll
            for (int j = 0; j < 4; ++j) acc[mt][nt][j] = 0.f;

    const int NST = K / KC;
    load_stage(A, Bt, m0, n0, 0,  K, sb,             tid);
    load_stage(A, Bt, m0, n0, KC, K, sb + STG_BYTES, tid);

    const int a_row  = wm * 64 + (lane & 15);
    const int a_csel = lane >> 4;
    const int a_sx   = a_row & 7;
    const uint32_t a_base = (uint32_t)a_row * 128;
    const int b_row  = wn * 64 + (lane & 7) + ((lane & 16) ? 8 : 0);
    const int b_csel = (lane >> 3) & 1;
    const int b_sx   = b_row & 7;
    const uint32_t b_base = B_OFF + (uint32_t)b_row * 128;

    for (int s = 0; s < NST; ++s) {
        const uint32_t buf = sb + (uint32_t)(s % NSTAGE) * STG_BYTES;
        CP_WAIT1();
        __syncthreads();
        if (s + 2 < NST)
            load_stage(A, Bt, m0, n0, (s + 2) * KC, K,
                       sb + (uint32_t)((s + 2) % NSTAGE) * STG_BYTES, tid);
        else
            CP_COMMIT();

        #pragma unroll
        for (int j = 0; j < 4; ++j) {
            uint32_t af[4][4], bf[4][4];
            const uint32_t a_co = ((2 * j + a_csel) ^ a_sx) * 16;
            const uint32_t b_co = ((2 * j + b_csel) ^ b_sx) * 16;
            #pragma unroll
            for (int mt = 0; mt < 4; ++mt)
                LDSM4(af[mt], buf + a_base + mt * (16 * 128) + a_co);
            #pragma unroll
            for (int p = 0; p < 4; ++p)
                LDSM4(bf[p], buf + b_base + p * (16 * 128) + b_co);
            #pragma unroll
            for (int p = 0; p < 4; ++p)
                #pragma unroll
                for (int mt = 0; mt < 4; ++mt) {
                    MMA_F16(acc[mt][2 * p],     af[mt], bf[p][0], bf[p][1]);
                    MMA_F16(acc[mt][2 * p + 1], af[mt], bf[p][2], bf[p][3]);
                }
        }
    }

    #pragma unroll
    for (int nt = 0; nt < 8; ++nt) {
        const int col = n0 + wn * 64 + nt * 8 + (lane & 3) * 2;
        const float2 bi = *(const float2*)&bias[col];
        #pragma unroll
        for (int mt = 0; mt < 4; ++mt) {
            const int row = m0 + wm * 64 + mt * 16 + (lane >> 2);
            if (OUT_HALF) {
                __half* C = (__half*)Cv;
                *(__half2*)&C[(size_t)row * N + col] =
                    __floats2half2_rn(acc[mt][nt][0] + bi.x, acc[mt][nt][1] + bi.y);
                *(__half2*)&C[(size_t)(row + 8) * N + col] =
                    __floats2half2_rn(acc[mt][nt][2] + bi.x, acc[mt][nt][3] + bi.y);
            } else {
                float* C = (float*)Cv;
                *(float2*)&C[(size_t)row * N + col] =
                    make_float2(acc[mt][nt][0] + bi.x, acc[mt][nt][1] + bi.y);
                *(float2*)&C[(size_t)(row + 8) * N + col] =
                    make_float2(acc[mt][nt][2] + bi.x, acc[mt][nt][3] + bi.y);
            }
        }
    }
}

// ---------------------------------------------------------------------------
// x -> fp16
// ---------------------------------------------------------------------------
__global__ void xconv_kernel(const float* __restrict__ X, __half* __restrict__ H, int n4)
{
    int i = blockIdx.x * blockDim.x + threadIdx.x;
    if (i >= n4) return;
    float4 v = ((const float4*)X)[i];
    ((__half2*)H)[2 * i]     = __floats2half2_rn(v.x, v.y);
    ((__half2*)H)[2 * i + 1] = __floats2half2_rn(v.z, v.w);
}

// ---------------------------------------------------------------------------
// W[K][N] -> W^T fp16 [N][K]
// ---------------------------------------------------------------------------
__global__ void wconv_kernel(const float* __restrict__ W, __half* __restrict__ Wt,
                             int K, int N)
{
    __shared__ float t[32][33];
    const int nb = blockIdx.x * 32, kb = blockIdx.y * 32;
    const int tx = threadIdx.x, ty = threadIdx.y;
    #pragma unroll
    for (int j = 0; j < 4; ++j)
        t[ty + 8 * j][tx] = W[(size_t)(kb + ty + 8 * j) * N + nb + tx];
    __syncthreads();
    #pragma unroll
    for (int j = 0; j < 4; ++j) {
        int n = nb + ty + 8 * j, k = kb + tx;
        Wt[(size_t)n * K + k] = __float2half_rn(t[tx][ty + 8 * j]);
    }
}

// ---------------------------------------------------------------------------
// Tensor-core windowed attention. One warp per (window, head): K/V/Q gathered
// into warp-private swizzled SMEM (fp16, raw copies), Q·K^T and P·V via
// mma.sync; softmax on fp32 C-frags with quad shuffles; P converted to
// A-frags in-register (C-frag layout == A-frag k8 halves). No __syncthreads.
// Block = 128 thr = 4 warps = 4 heads. Warp SMEM: K 8KB | V 8KB | Qp 2KB.
// ---------------------------------------------------------------------------
#define AW_BYTES 18432
#define ATTN_SMEM (4 * AW_BYTES)   // 73728

__global__ __launch_bounds__(128)
void attn_kernel(const __half* __restrict__ qkv, __half* __restrict__ oh)
{
    extern __shared__ char asmem[];
    const int tid = threadIdx.x, wid = tid >> 5, lane = tid & 31;
    const int w = blockIdx.x, b = blockIdx.z;
    const int h = blockIdx.y * 4 + wid;

    const uint32_t wb = smem_u32(asmem) + (uint32_t)wid * AW_BYTES;
    const uint32_t KS = wb, VS = wb + 8192, QP = wb + 16384;

    const __half* bp = qkv + (size_t)b * NTOK * DIM3 + h * HD;
    const uint32_t lsub = ((lane >> 2) << 0);            // 16B chunk index
    const uint32_t lrem = (uint32_t)((lane & 3) << 2);   // byte within chunk

    // gather K, V rows (token n = t*49 + w), store swizzled
    #pragma unroll 4
    for (int t = 0; t < TPW; ++t) {
        const __half* rp = bp + (size_t)(t * NW + w) * DIM3;
        uint32_t kv = *(const uint32_t*)((const __half2*)(rp + DIMC) + lane);
        uint32_t vv = *(const uint32_t*)((const __half2*)(rp + 2 * DIMC) + lane);
        uint32_t d = (uint32_t)t * 128 + (((lsub ^ (t & 7)) << 4)) + lrem;
        STS32(KS + d, kv);
        STS32(VS + d, vv);
    }
    // pooled Q: max over s of q[t = s*16 + qi] (fp16 max is exact on fp16)
    #pragma unroll
    for (int qi = 0; qi < WS; ++qi) {
        __half2 m = ((const __half2*)(bp + (size_t)(qi * NW + w) * DIM3))[lane];
        #pragma unroll
        for (int s = 1; s < 4; ++s) {
            __half2 v = ((const __half2*)
                (bp + (size_t)((s * WS + qi) * NW + w) * DIM3))[lane];
            m = __hmax2(m, v);
        }
        uint32_t d = (uint32_t)qi * 128 + (((lsub ^ (qi & 7)) << 4)) + lrem;
        STS32(QP + d, *(uint32_t*)&m);
    }
    __syncwarp();

    // ---- logits = Qp @ K^T  (16 x 64, fp32 acc) ----
    float sa[8][4];
    #pragma unroll
    for (int f = 0; f < 8; ++f)
        #pragma unroll
        for (int j = 0; j < 4; ++j) sa[f][j] = 0.f;

    const int aro = lane & 15, acs = lane >> 4, asx = aro & 7;
    const int bro = (lane & 7) + ((lane & 16) ? 8 : 0);
    const int bcs = (lane >> 3) & 1, bsx = bro & 7;

    #pragma unroll
    for (int j = 0; j < 4; ++j) {
        uint32_t qf[4];
        LDSM4(qf, QP + (uint32_t)aro * 128 + (((2 * j + acs) ^ asx) << 4));
        #pragma unroll
        for (int p = 0; p < 4; ++p) {
            uint32_t kf[4];
            LDSM4(kf, KS + (uint32_t)(p * 16 + bro) * 128
                        + (((2 * j + bcs) ^ bsx) << 4));
            MMA_F16(sa[2 * p],     qf, kf[0], kf[1]);
            MMA_F16(sa[2 * p + 1], qf, kf[2], kf[3]);
        }
    }

    // ---- softmax over 64 keys; rows r1 = lane>>2, r2 = r1+8 ----
    float m1 = -3.0e38f, m2 = -3.0e38f;
    #pragma unroll
    for (int f = 0; f < 8; ++f) {
        #pragma unroll
        for (int j = 0; j < 4; ++j) sa[f][j] *= 0.125f;
        m1 = fmaxf(m1, fmaxf(sa[f][0], sa[f][1]));
        m2 = fmaxf(m2, fmaxf(sa[f][2], sa[f][3]));
    }
    m1 = fmaxf(m1, __shfl_xor_sync(0xffffffffu, m1, 1));
    m1 = fmaxf(m1, __shfl_xor_sync(0xffffffffu, m1, 2));
    m2 = fmaxf(m2, __shfl_xor_sync(0xffffffffu, m2, 1));
    m2 = fmaxf(m2, __shfl_xor_sync(0xffffffffu, m2, 2));
    float s1 = 0.f, s2 = 0.f;
    #pragma unroll
    for (int f = 0; f < 8; ++f) {
        sa[f][0] = __expf(sa[f][0] - m1);
        sa[f][1] = __expf(sa[f][1] - m1);
        sa[f][2] = __expf(sa[f][2] - m2);
        sa[f][3] = __expf(sa[f][3] - m2);
        s1 += sa[f][0] + sa[f][1];
        s2 += sa[f][2] + sa[f][3];
    }
    s1 += __shfl_xor_sync(0xffffffffu, s1, 1);
    s1 += __shfl_xor_sync(0xffffffffu, s1, 2);
    s2 += __shfl_xor_sync(0xffffffffu, s2, 1);
    s2 += __shfl_xor_sync(0xffffffffu, s2, 2);
    const float i1 = 1.f / s1, i2 = 1.f / s2;

    // P -> fp16 A-fragments (C-frag pairs = A-frag k8 halves; no shuffles)
    uint32_t pa[4][4];
    #pragma unroll
    for (int i = 0; i < 4; ++i) {
        const int f0 = 2 * i, f1 = 2 * i + 1;
        __half2 t0 = __floats2half2_rn(sa[f0][0] * i1, sa[f0][1] * i1);
        __half2 t1 = __floats2half2_rn(sa[f0][2] * i2, sa[f0][3] * i2);
        __half2 t2 = __floats2half2_rn(sa[f1][0] * i1, sa[f1][1] * i1);
        __half2 t3 = __floats2half2_rn(sa[f1][2] * i2, sa[f1][3] * i2);
        pa[i][0] = *(uint32_t*)&t0;
        pa[i][1] = *(uint32_t*)&t1;
        pa[i][2] = *(uint32_t*)&t2;
        pa[i][3] = *(uint32_t*)&t3;
    }

    // ---- o = P @ V  (V^T fragments via trans-ldmatrix) ----
    float oa[8][4];
    #pragma unroll
    for (int f = 0; f < 8; ++f)
        #pragma unroll
        for (int j = 0; j < 4; ++j) oa[f][j] = 0.f;

    const int vro = (lane & 7) + ((lane & 8) ? 8 : 0);   // t within 16-block
    const int vcs = (lane >> 4) & 1;                     // +16B col half
    const int vsx = lane & 7;                            // (trow & 7)
    #pragma unroll
    for (int i = 0; i < 4; ++i) {
        const uint32_t trow = (uint32_t)(i * 16 + vro);
        #pragma unroll
        for (int p = 0; p < 4; ++p) {
            uint32_t vf[4];
            LDSM4T(vf, VS + trow * 128 + (((2 * p + vcs) ^ vsx) << 4));
            MMA_F16(oa[2 * p],     pa[i], vf[0], vf[1]);
            MMA_F16(oa[2 * p + 1], pa[i], vf[2], vf[3]);
        }
    }

    // ---- store: pooled token m = qi*49 + w, channel h*64 + d ----
    const int r1 = lane >> 2, c0 = (lane & 3) * 2;
    const size_t ob = (size_t)b * MTOK * DIMC + h * HD;
    const size_t tok1 = (size_t)(r1 * NW + w) * DIMC;
    const size_t tok2 = (size_t)((r1 + 8) * NW + w) * DIMC;
    #pragma unroll
    for (int f = 0; f < 8; ++f) {
        const int d = f * 8 + c0;
        *(__half2*)&oh[ob + tok1 + d] = __floats2half2_rn(oa[f][0], oa[f][1]);
        *(__half2*)&oh[ob + tok2 + d] = __floats2half2_rn(oa[f][2], oa[f][3]);
    }
}

// ---------------------------------------------------------------------------
extern "C" void kernel_launch(void* const* d_in, const int* in_sizes, int n_in,
                              void* d_out, int out_size)
{
    const float* x     = (const float*)d_in[0];
    const float* Wqkv  = (const float*)d_in[1];
    const float* bqkv  = (const float*)d_in[2];
    const float* Wproj = (const float*)d_in[3];
    const float* bproj = (const float*)d_in[4];
    float* out = (float*)d_out;

    __half *qkvp, *xh, *oh, *wt;
    cudaGetSymbolAddress((void**)&qkvp, g_qkv);
    cudaGetSymbolAddress((void**)&xh, g_xh);
    cudaGetSymbolAddress((void**)&oh, g_oh);
    cudaGetSymbolAddress((void**)&wt, g_wt);

    cudaFuncSetAttribute(gemm_f16_kernel<0>,
                         cudaFuncAttributeMaxDynamicSharedMemorySize, GEMM_SMEM);
    cudaFuncSetAttribute(gemm_f16_kernel<1>,
                         cudaFuncAttributeMaxDynamicSharedMemorySize, GEMM_SMEM);
    cudaFuncSetAttribute(attn_kernel,
                         cudaFuncAttributeMaxDynamicSharedMemorySize, ATTN_SMEM);

    // 0a) x -> fp16
    {
        int n4 = (int)(NELEM_X / 4);
        xconv_kernel<<<n4 / 256, 256>>>(x, xh, n4);
    }
    // 0b) transpose weights -> fp16 [N][K]
    {
        dim3 bdim(32, 8);
        wconv_kernel<<<dim3(DIM3 / 32, DIMC / 32), bdim>>>(Wqkv, wt, DIMC, DIM3);
        wconv_kernel<<<dim3(DIMC / 32, DIMC / 32), bdim>>>(Wproj, wt + WQT_ELEMS,
                                                           DIMC, DIMC);
    }
    // 1) QKV projection -> fp16 qkv
    {
        dim3 grid(DIM3 / TILE_N, (B_ * NTOK) / TILE_M);   // (18, 392)
        gemm_f16_kernel<1><<<grid, 256, GEMM_SMEM>>>(xh, wt, bqkv, qkvp,
                                                     B_ * NTOK, DIM3, KDIM);
    }
    // 2) tensor-core windowed attention with query max-pool
    {
        dim3 grid(NW, HEADS / 4, B_);                     // (49, 3, 32)
        attn_kernel<<<grid, 128, ATTN_SMEM>>>(qkvp, oh);
    }
    // 3) output projection -> fp32 out
    {
        dim3 grid(DIMC / TILE_N, (B_ * MTOK) / TILE_M);   // (6, 98)
        gemm_f16_kernel<0><<<grid, 256, GEMM_SMEM>>>(oh, wt + WQT_ELEMS,
                                                     bproj, out, B_ * MTOK, DIMC, KDIM);
    }
}

// round 11
// speedup vs baseline: 1.5475x; 1.5475x over previous
#include <cuda_runtime.h>
#include <cuda_fp16.h>
#include <cstdint>

// Problem constants
#define B_      32
#define NTOK    3136
#define DIMC    768
#define DIM3    2304
#define HEADS   12
#define HD      64
#define NW      49
#define WS      16
#define TPW     64
#define MTOK    784
#define KDIM    768

#define NELEM_X   ((size_t)B_ * NTOK * DIMC)
#define NELEM_O   ((size_t)B_ * MTOK * DIMC)
#define WQT_ELEMS ((size_t)DIM3 * DIMC)
#define WPT_ELEMS ((size_t)DIMC * DIMC)

// Scratch (device globals: allocation-free rule)
__device__ __half g_qkv[(size_t)B_ * NTOK * DIM3];   // fp16 qkv
__device__ __half g_xh[NELEM_X];
__device__ __half g_oh[NELEM_O];
__device__ __half g_wt[WQT_ELEMS + WPT_ELEMS];       // [N][K] transposed, fp16

// ---------------------------------------------------------------------------
// PTX helpers
// ---------------------------------------------------------------------------
__device__ __forceinline__ uint32_t smem_u32(const void* p) {
    uint32_t a;
    asm("{ .reg .u64 t; cvta.to.shared.u64 t, %1; cvt.u32.u64 %0, t; }" : "=r"(a) : "l"(p));
    return a;
}
#define CP_ASYNC16(dst, src) \
    asm volatile("cp.async.cg.shared.global [%0], [%1], 16;" :: "r"(dst), "l"(src))
#define CP_COMMIT() asm volatile("cp.async.commit_group;" ::: "memory")
#define CP_WAIT1()  asm volatile("cp.async.wait_group 1;" ::: "memory")

#define LDSM4(r, addr) \
    asm volatile("ldmatrix.sync.aligned.m8n8.x4.shared.b16 {%0,%1,%2,%3}, [%4];" \
                 : "=r"((r)[0]), "=r"((r)[1]), "=r"((r)[2]), "=r"((r)[3]) : "r"(addr))
#define LDSM4T(r, addr) \
    asm volatile("ldmatrix.sync.aligned.m8n8.x4.trans.shared.b16 {%0,%1,%2,%3}, [%4];" \
                 : "=r"((r)[0]), "=r"((r)[1]), "=r"((r)[2]), "=r"((r)[3]) : "r"(addr))

#define MMA_F16(c, a, b0, b1) \
    asm volatile("mma.sync.aligned.m16n8k16.row.col.f32.f16.f16.f32 " \
                 "{%0,%1,%2,%3}, {%4,%5,%6,%7}, {%8,%9}, {%0,%1,%2,%3};" \
                 : "+f"((c)[0]), "+f"((c)[1]), "+f"((c)[2]), "+f"((c)[3]) \
                 : "r"((a)[0]), "r"((a)[1]), "r"((a)[2]), "r"((a)[3]), \
                   "r"(b0), "r"(b1))

// ---------------------------------------------------------------------------
// fp16 GEMM (R8 config — best measured; at fp32-acc HMMA floor).
// Tile 128x128, 8 warps (warp tile 32x64), KC=64, 3-stage cp.async ring.
// ---------------------------------------------------------------------------
#define TILE_MN   128
#define KC        64
#define MAT_BYTES 16384
#define STG_BYTES 32768
#define NSTAGE    3
#define GEMM_SMEM (NSTAGE * STG_BYTES)  // 98304

__device__ __forceinline__ void load_stage(
    const __half* __restrict__ A, const __half* __restrict__ Bt,
    int m0, int n0, int kt, int K, uint32_t buf, int tid)
{
    #pragma unroll
    for (int i = 0; i < 8; ++i) {
        int idx = tid + i * 256;
        int mat = idx >> 10;
        int c   = idx & 1023;
        int r   = c >> 3;
        int g   = c & 7;
        const __half* src = (mat ? Bt : A)
                          + (size_t)((mat ? n0 : m0) + r) * K + kt + g * 8;
        uint32_t dst = buf + mat * MAT_BYTES + r * 128 + ((g ^ (r & 7)) * 16);
        CP_ASYNC16(dst, src);
    }
    CP_COMMIT();
}

template <int OUT_HALF>
__global__ __launch_bounds__(256, 2)
void gemm_f16_kernel(const __half* __restrict__ A, const __half* __restrict__ Bt,
                     const float* __restrict__ bias, void* __restrict__ Cv,
                     int M, int N, int K)
{
    extern __shared__ char smem[];
    const uint32_t sb = smem_u32(smem);
    const int tid = threadIdx.x, wid = tid >> 5, lane = tid & 31;
    const int wm = wid & 3, wn = wid >> 2;
    const int m0 = blockIdx.y * TILE_MN;
    const int n0 = blockIdx.x * TILE_MN;

    float acc[2][8][4];
    #pragma unroll
    for (int mt = 0; mt < 2; ++mt)
        #pragma unroll
        for (int nt = 0; nt < 8; ++nt)
            #pragma unroll
            for (int j = 0; j < 4; ++j) acc[mt][nt][j] = 0.f;

    const int NST = K / KC;
    load_stage(A, Bt, m0, n0, 0,  K, sb,             tid);
    load_stage(A, Bt, m0, n0, KC, K, sb + STG_BYTES, tid);

    const int a_row  = wm * 32 + (lane & 15);
    const int a_csel = lane >> 4;
    const int a_sx   = a_row & 7;
    const uint32_t a_base = (uint32_t)a_row * 128;
    const int b_row  = wn * 64 + (lane & 7) + ((lane & 16) ? 8 : 0);
    const int b_csel = (lane >> 3) & 1;
    const int b_sx   = b_row & 7;
    const uint32_t b_base = MAT_BYTES + (uint32_t)b_row * 128;

    for (int s = 0; s < NST; ++s) {
        const uint32_t buf = sb + (uint32_t)(s % NSTAGE) * STG_BYTES;
        CP_WAIT1();
        __syncthreads();
        if (s + 2 < NST)
            load_stage(A, Bt, m0, n0, (s + 2) * KC, K,
                       sb + (uint32_t)((s + 2) % NSTAGE) * STG_BYTES, tid);
        else
            CP_COMMIT();

        #pragma unroll
        for (int j = 0; j < 4; ++j) {
            uint32_t af[2][4], bf[4][4];
            const uint32_t a_co = ((2 * j + a_csel) ^ a_sx) * 16;
            const uint32_t b_co = ((2 * j + b_csel) ^ b_sx) * 16;
            #pragma unroll
            for (int mt = 0; mt < 2; ++mt)
                LDSM4(af[mt], buf + a_base + mt * (16 * 128) + a_co);
            #pragma unroll
            for (int p = 0; p < 4; ++p)
                LDSM4(bf[p], buf + b_base + p * (16 * 128) + b_co);
            #pragma unroll
            for (int p = 0; p < 4; ++p)
                #pragma unroll
                for (int mt = 0; mt < 2; ++mt) {
                    MMA_F16(acc[mt][2 * p],     af[mt], bf[p][0], bf[p][1]);
                    MMA_F16(acc[mt][2 * p + 1], af[mt], bf[p][2], bf[p][3]);
                }
        }
    }

    #pragma unroll
    for (int nt = 0; nt < 8; ++nt) {
        const int col = n0 + wn * 64 + nt * 8 + (lane & 3) * 2;
        const float2 bi = *(const float2*)&bias[col];
        #pragma unroll
        for (int mt = 0; mt < 2; ++mt) {
            const int row = m0 + wm * 32 + mt * 16 + (lane >> 2);
            if (OUT_HALF) {
                __half* C = (__half*)Cv;
                *(__half2*)&C[(size_t)row * N + col] =
                    __floats2half2_rn(acc[mt][nt][0] + bi.x, acc[mt][nt][1] + bi.y);
                *(__half2*)&C[(size_t)(row + 8) * N + col] =
                    __floats2half2_rn(acc[mt][nt][2] + bi.x, acc[mt][nt][3] + bi.y);
            } else {
                float* C = (float*)Cv;
                *(float2*)&C[(size_t)row * N + col] =
                    make_float2(acc[mt][nt][0] + bi.x, acc[mt][nt][1] + bi.y);
                *(float2*)&C[(size_t)(row + 8) * N + col] =
                    make_float2(acc[mt][nt][2] + bi.x, acc[mt][nt][3] + bi.y);
            }
        }
    }
}

// ---------------------------------------------------------------------------
// x -> fp16
// ---------------------------------------------------------------------------
__global__ void xconv_kernel(const float* __restrict__ X, __half* __restrict__ H, int n4)
{
    int i = blockIdx.x * blockDim.x + threadIdx.x;
    if (i >= n4) return;
    float4 v = ((const float4*)X)[i];
    ((__half2*)H)[2 * i]     = __floats2half2_rn(v.x, v.y);
    ((__half2*)H)[2 * i + 1] = __floats2half2_rn(v.z, v.w);
}

// ---------------------------------------------------------------------------
// W[K][N] -> W^T fp16 [N][K]
// ---------------------------------------------------------------------------
__global__ void wconv_kernel(const float* __restrict__ W, __half* __restrict__ Wt,
                             int K, int N)
{
    __shared__ float t[32][33];
    const int nb = blockIdx.x * 32, kb = blockIdx.y * 32;
    const int tx = threadIdx.x, ty = threadIdx.y;
    #pragma unroll
    for (int j = 0; j < 4; ++j)
        t[ty + 8 * j][tx] = W[(size_t)(kb + ty + 8 * j) * N + nb + tx];
    __syncthreads();
    #pragma unroll
    for (int j = 0; j < 4; ++j) {
        int n = nb + ty + 8 * j, k = kb + tx;
        Wt[(size_t)n * K + k] = __float2half_rn(t[tx][ty + 8 * j]);
    }
}

// ---------------------------------------------------------------------------
// Tensor-core windowed attention, block-cooperative gather.
// Block = 128 thr = one (b, w, h). Phases:
//   1) coalesced gather K/V/Qpool into swizzled fp16 SMEM (plain C++ stores)
//   2) QK^T: warp j owns key-block 16j (mma.sync, fp32 acc) -> LG fp32
//   3) softmax (fp32, warp per 4 rows) -> PS fp16 swizzled
//   4) P@V: warp j owns d-block 16j (A via LDSM, V^T via trans-LDSM)
// Swizzle: 64-fp16 rows (128B), 16B chunk g at (g ^ (row&7)).
// ---------------------------------------------------------------------------
__global__ __launch_bounds__(128)
void attn_kernel(const __half* __restrict__ qkv, __half* __restrict__ oh)
{
    __shared__ __half KS[TPW * 64];
    __shared__ __half VS[TPW * 64];
    __shared__ __half QP[WS * 64];
    __shared__ __half PS[WS * 64];
    __shared__ float  LG[WS][68];

    const int tid = threadIdx.x, wj = tid >> 5, lane = tid & 31;
    const int w = blockIdx.x, h = blockIdx.y, b = blockIdx.z;
    const __half* bp = qkv + (size_t)b * NTOK * DIM3 + h * HD;

    // ---- phase 1: gather (coalesced, compiler-pipelined) ----
    uint32_t* ks32 = (uint32_t*)KS;
    uint32_t* vs32 = (uint32_t*)VS;
    uint32_t* qp32 = (uint32_t*)QP;
    #pragma unroll
    for (int i = 0; i < 16; ++i) {
        int idx = tid + i * 128;          // 0..2047 (uint32 slots)
        int t = idx >> 5, d2 = idx & 31;
        const __half* rowp = bp + (size_t)(t * NW + w) * DIM3;
        uint32_t kv = *(const uint32_t*)(rowp + DIMC + 2 * d2);
        uint32_t vv = *(const uint32_t*)(rowp + 2 * DIMC + 2 * d2);
        int slot = t * 32 + (((d2 >> 2) ^ (t & 7)) << 2) + (d2 & 3);
        ks32[slot] = kv;
        vs32[slot] = vv;
    }
    #pragma unroll
    for (int i = 0; i < 4; ++i) {
        int idx = tid + i * 128;          // 0..511
        int qi = idx >> 5, d2 = idx & 31;
        uint32_t u = *(const uint32_t*)(bp + (size_t)(qi * NW + w) * DIM3 + 2 * d2);
        __half2 m = *(__half2*)&u;
        #pragma unroll
        for (int s = 1; s < 4; ++s) {
            uint32_t u2 = *(const uint32_t*)
                (bp + (size_t)((s * WS + qi) * NW + w) * DIM3 + 2 * d2);
            m = __hmax2(m, *(__half2*)&u2);
        }
        int slot = qi * 32 + (((d2 >> 2) ^ (qi & 7)) << 2) + (d2 & 3);
        qp32[slot] = *(uint32_t*)&m;
    }
    __syncthreads();

    const uint32_t KSa = smem_u32(KS), VSa = smem_u32(VS);
    const uint32_t QPa = smem_u32(QP), PSa = smem_u32(PS);

    // common fragment geometry
    const int aro = lane & 15, acs = lane >> 4, asx = aro & 7;
    const int r1 = lane >> 2, c0 = (lane & 3) * 2;

    // ---- phase 2: logits tile [16 x keys 16wj..16wj+15] ----
    {
        float sa[2][4];
        #pragma unroll
        for (int f = 0; f < 2; ++f)
            #pragma unroll
            for (int j = 0; j < 4; ++j) sa[f][j] = 0.f;
        const int bro = (lane & 7) + ((lane & 16) ? 8 : 0);
        const int bcs = (lane >> 3) & 1, bsx = bro & 7;
        #pragma unroll
        for (int k = 0; k < 4; ++k) {
            uint32_t qf[4], kf[4];
            LDSM4(qf, QPa + (uint32_t)aro * 128 + (((2 * k + acs) ^ asx) << 4));
            LDSM4(kf, KSa + (uint32_t)(wj * 16 + bro) * 128
                        + (((2 * k + bcs) ^ bsx) << 4));
            MMA_F16(sa[0], qf, kf[0], kf[1]);
            MMA_F16(sa[1], qf, kf[2], kf[3]);
        }
        #pragma unroll
        for (int f = 0; f < 2; ++f) {
            const int c = wj * 16 + f * 8 + c0;
            LG[r1][c]         = sa[f][0] * 0.125f;
            LG[r1][c + 1]     = sa[f][1] * 0.125f;
            LG[r1 + 8][c]     = sa[f][2] * 0.125f;
            LG[r1 + 8][c + 1] = sa[f][3] * 0.125f;
        }
    }
    __syncthreads();

    // ---- phase 3: softmax (warp wj: rows 4wj..4wj+3) -> PS fp16 swizzled ----
    #pragma unroll
    for (int r = wj * 4; r < wj * 4 + 4; ++r) {
        float x0 = LG[r][lane], x1 = LG[r][lane + 32];
        float m = fmaxf(x0, x1);
        #pragma unroll
        for (int o = 16; o; o >>= 1)
            m = fmaxf(m, __shfl_xor_sync(0xffffffffu, m, o));
        float e0 = __expf(x0 - m), e1 = __expf(x1 - m);
        float s = e0 + e1;
        #pragma unroll
        for (int o = 16; o; o >>= 1)
            s += __shfl_xor_sync(0xffffffffu, s, o);
        float inv = 1.f / s;
        // col = lane -> chunk lane>>3; col = lane+32 -> chunk (lane>>3)+4
        PS[r * 64 + ((((lane >> 3))     ^ (r & 7)) << 3) + (lane & 7)] =
            __float2half_rn(e0 * inv);
        PS[r * 64 + ((((lane >> 3) + 4) ^ (r & 7)) << 3) + (lane & 7)] =
            __float2half_rn(e1 * inv);
    }
    __syncthreads();

    // ---- phase 4: o tile [16 x d 16wj..16wj+15] = P @ V ----
    {
        float oa[2][4];
        #pragma unroll
        for (int f = 0; f < 2; ++f)
            #pragma unroll
            for (int j = 0; j < 4; ++j) oa[f][j] = 0.f;
        const int vro = (lane & 7) + ((lane & 8) ? 8 : 0);
        const int vcs = (lane >> 4) & 1, vsx = vro & 7;
        #pragma unroll
        for (int i = 0; i < 4; ++i) {
            uint32_t pf[4], vf[4];
            LDSM4(pf, PSa + (uint32_t)aro * 128 + (((2 * i + acs) ^ asx) << 4));
            LDSM4T(vf, VSa + (uint32_t)(i * 16 + vro) * 128
                         + (((2 * wj + vcs) ^ vsx) << 4));
            MMA_F16(oa[0], pf, vf[0], vf[1]);
            MMA_F16(oa[1], pf, vf[2], vf[3]);
        }
        const size_t ob = (size_t)b * MTOK * DIMC + h * HD;
        const size_t tok1 = (size_t)(r1 * NW + w) * DIMC;
        const size_t tok2 = (size_t)((r1 + 8) * NW + w) * DIMC;
        #pragma unroll
        for (int f = 0; f < 2; ++f) {
            const int d = wj * 16 + f * 8 + c0;
            *(__half2*)&oh[ob + tok1 + d] = __floats2half2_rn(oa[f][0], oa[f][1]);
            *(__half2*)&oh[ob + tok2 + d] = __floats2half2_rn(oa[f][2], oa[f][3]);
        }
    }
}

// ---------------------------------------------------------------------------
extern "C" void kernel_launch(void* const* d_in, const int* in_sizes, int n_in,
                              void* d_out, int out_size)
{
    const float* x     = (const float*)d_in[0];
    const float* Wqkv  = (const float*)d_in[1];
    const float* bqkv  = (const float*)d_in[2];
    const float* Wproj = (const float*)d_in[3];
    const float* bproj = (const float*)d_in[4];
    float* out = (float*)d_out;

    __half *qkvp, *xh, *oh, *wt;
    cudaGetSymbolAddress((void**)&qkvp, g_qkv);
    cudaGetSymbolAddress((void**)&xh, g_xh);
    cudaGetSymbolAddress((void**)&oh, g_oh);
    cudaGetSymbolAddress((void**)&wt, g_wt);

    cudaFuncSetAttribute(gemm_f16_kernel<0>,
                         cudaFuncAttributeMaxDynamicSharedMemorySize, GEMM_SMEM);
    cudaFuncSetAttribute(gemm_f16_kernel<1>,
                         cudaFuncAttributeMaxDynamicSharedMemorySize, GEMM_SMEM);

    // 0a) x -> fp16
    {
        int n4 = (int)(NELEM_X / 4);
        xconv_kernel<<<n4 / 256, 256>>>(x, xh, n4);
    }
    // 0b) transpose weights -> fp16 [N][K]
    {
        dim3 bdim(32, 8);
        wconv_kernel<<<dim3(DIM3 / 32, DIMC / 32), bdim>>>(Wqkv, wt, DIMC, DIM3);
        wconv_kernel<<<dim3(DIMC / 32, DIMC / 32), bdim>>>(Wproj, wt + WQT_ELEMS,
                                                           DIMC, DIMC);
    }
    // 1) QKV projection -> fp16 qkv
    {
        dim3 grid(DIM3 / TILE_MN, (B_ * NTOK) / TILE_MN);   // (18, 784)
        gemm_f16_kernel<1><<<grid, 256, GEMM_SMEM>>>(xh, wt, bqkv, qkvp,
                                                     B_ * NTOK, DIM3, KDIM);
    }
    // 2) tensor-core windowed attention with query max-pool
    {
        dim3 grid(NW, HEADS, B_);                           // (49, 12, 32)
        attn_kernel<<<grid, 128>>>(qkvp, oh);
    }
    // 3) output projection -> fp32 out
    {
        dim3 grid(DIMC / TILE_MN, (B_ * MTOK) / TILE_MN);   // (6, 196)
        gemm_f16_kernel<0><<<grid, 256, GEMM_SMEM>>>(oh, wt + WQT_ELEMS,
                                                     bproj, out, B_ * MTOK, DIMC, KDIM);
    }
}